// round 15
// baseline (speedup 1.0000x reference)
#include <cuda_runtime.h>
#include <cuda_fp16.h>
#include <stdint.h>

#define B_TOK 8192
#define DIM   2048
#define NEXP  8

#define BM 128
#define BN 128
#define BK 128
#define NKC (DIM / BK)          // 16
#define NNT (DIM / BN)          // 16
#define MAXTILES 72
#define GTHREADS 256            // 8 compute warps

#define TILE_A 32768            // 128m x 128k fp16, 2 k-subtiles of 16KB, SW128
#define TILE_B 32768            // 128k x 128n fp16, 2 n-subtiles of 16KB, SW128
#define STAGE_SZ (TILE_A + TILE_B)   // 65536
#define OFF_B TILE_A
#define OFF_MB (2 * STAGE_SZ)        // 131072
#define OFF_ROWS (OFF_MB + 64)
#define SMEM_REQ (OFF_ROWS + 512 + 1024)

#define NTB 32

// -------- device scratch --------
__device__ int d_bh[NTB][NEXP];
__device__ int d_boff[NTB][NEXP];
__device__ int d_poff[NEXP + 1];
__device__ int d_is64 = 1;           // monotone latch
__device__ int d_done = 0;
__device__ int d_perm[MAXTILES * 128];

__device__ volatile int f_a[MAXTILES * NKC];        // 1152 A-tile flags: 0/1/2
__device__ volatile int f_b[NEXP * NNT * NKC];      // 2048 B-tile flags: 0/1/2

__device__ __align__(128) char g_xa[(size_t)MAXTILES * NKC * TILE_A];       // 36 MB
__device__ __align__(128) char g_wb[(size_t)NEXP * NNT * NKC * TILE_B];     // 64 MB

// ======================= helpers =======================
__device__ __forceinline__ uint32_t smem_u32(const void* p) {
    uint32_t a;
    asm("{ .reg .u64 t; cvta.to.shared.u64 t, %1; cvt.u32.u64 %0, t; }" : "=r"(a) : "l"(p));
    return a;
}
__device__ __forceinline__ uint32_t sw128(uint32_t off) { return off ^ ((off >> 3) & 0x70); }

__device__ __forceinline__ void ldsm_x4(uint32_t* r, uint32_t addr) {
    asm volatile("ldmatrix.sync.aligned.m8n8.x4.shared.b16 {%0,%1,%2,%3}, [%4];"
                 : "=r"(r[0]), "=r"(r[1]), "=r"(r[2]), "=r"(r[3]) : "r"(addr));
}
__device__ __forceinline__ void ldsm_x4_t(uint32_t* r, uint32_t addr) {
    asm volatile("ldmatrix.sync.aligned.m8n8.x4.trans.shared.b16 {%0,%1,%2,%3}, [%4];"
                 : "=r"(r[0]), "=r"(r[1]), "=r"(r[2]), "=r"(r[3]) : "r"(addr));
}
__device__ __forceinline__ void mma16816(float* d, const uint32_t* a, uint32_t b0, uint32_t b1) {
    asm volatile(
        "mma.sync.aligned.m16n8k16.row.col.f32.f16.f16.f32 "
        "{%0,%1,%2,%3}, {%4,%5,%6,%7}, {%8,%9}, {%0,%1,%2,%3};"
        : "+f"(d[0]), "+f"(d[1]), "+f"(d[2]), "+f"(d[3])
        : "r"(a[0]), "r"(a[1]), "r"(a[2]), "r"(a[3]), "r"(b0), "r"(b1));
}
__device__ __forceinline__ void bulk_g2s(uint32_t dst, const void* src, uint32_t bytes, uint32_t mbar) {
    asm volatile(
        "{\n\t.reg .u64 g;\n\tcvta.to.global.u64 g, %1;\n\t"
        "cp.async.bulk.shared::cluster.global.mbarrier::complete_tx::bytes [%0], [g], %2, [%3];\n\t}"
        :: "r"(dst), "l"(src), "r"(bytes), "r"(mbar) : "memory");
}
#define MBARRIER_INIT(addr, cnt) \
    asm volatile("mbarrier.init.shared.b64 [%0], %1;" :: "r"((uint32_t)(addr)), "r"((uint32_t)(cnt)) : "memory")
#define MBARRIER_EXPECT_TX(addr, tx) \
    asm volatile("mbarrier.arrive.expect_tx.shared.b64 _, [%0], %1;" :: "r"((uint32_t)(addr)), "r"((uint32_t)(tx)) : "memory")
#define MBARRIER_WAIT_PARITY(addr, par) do { \
    uint32_t _m = (uint32_t)(addr); uint32_t _p = (uint32_t)(par); uint32_t _done; \
    asm volatile("{\n\t.reg .pred p;\n\t" \
        "mbarrier.try_wait.parity.acquire.cta.shared::cta.b64 p, [%1], %2;\n\t" \
        "selp.b32 %0, 1, 0, p;\n\t}" : "=r"(_done) : "r"(_m), "r"(_p) : "memory"); \
    if (!_done) { \
        asm volatile("{\n\t.reg .pred P1;\n\t" \
            "WL_%=:\n\tmbarrier.try_wait.parity.acquire.cta.shared::cta.b64 P1, [%0], %1, 0x989680;\n\t" \
            "@P1 bra.uni WD_%=;\n\tbra.uni WL_%=;\n\tWD_%=:\n\t}" \
            :: "r"(_m), "r"(_p) : "memory"); \
    } \
} while (0)

__device__ __forceinline__ int expert_of(const int* v, int i) { return d_is64 ? v[2 * i] : v[i]; }

// ---- 256-thread tile conversion bodies ----
// B tile (e,nt,kc): [128k x 128n] fp16, 2 n-subtiles of (128k x 64n), SW128.
__device__ __forceinline__ void convert_b_body(const float* __restrict__ W,
                                               int e, int nt, int kc, int t) {
    const float* Wb = W + ((size_t)e * DIM + kc * BK) * DIM + nt * BN;
    char* dst = g_wb + ((size_t)((e * NNT + nt) * NKC + kc)) * TILE_B;
#pragma unroll
    for (int i = 0; i < 8; i++) {
        int g = i * 256 + t;                 // 0..2047 granules of 8 n
        int k = g >> 4, c = g & 15;
        const float4* s4 = (const float4*)(Wb + (size_t)k * DIM + c * 8);
        float4 w0 = s4[0];
        float4 w1 = s4[1];
        __half2 h0 = __floats2half2_rn(w0.x, w0.y);
        __half2 h1 = __floats2half2_rn(w0.z, w0.w);
        __half2 h2 = __floats2half2_rn(w1.x, w1.y);
        __half2 h3 = __floats2half2_rn(w1.z, w1.w);
        uint4 val;
        val.x = *(uint32_t*)&h0; val.y = *(uint32_t*)&h1;
        val.z = *(uint32_t*)&h2; val.w = *(uint32_t*)&h3;
        *(uint4*)(dst + ((c >> 3) << 14) + sw128((uint32_t)(k * 128 + (c & 7) * 16))) = val;
    }
}
// A tile (mt,kc): [128m x 128k] fp16, 2 k-subtiles of (128m x 64k), SW128.
__device__ __forceinline__ void convert_a_body(const float* __restrict__ x,
                                               const int* rows, int kc, int t) {
#pragma unroll
    for (int i = 0; i < 16; i++) {
        int h = i * 256 + t;                 // 0..4095 granules of 4 k
        int r = h >> 5, Fl = h & 31;
        int grow = rows[r];
        uint2 hv = make_uint2(0u, 0u);
        if (grow >= 0) {
            float4 w = *(const float4*)(x + (size_t)grow * DIM + kc * BK + Fl * 4);
            __half2 h0 = __floats2half2_rn(w.x, w.y);
            __half2 h1 = __floats2half2_rn(w.z, w.w);
            hv.x = *(uint32_t*)&h0; hv.y = *(uint32_t*)&h1;
        }
        // dst resolved by caller-provided base via rows? no: compute here
        // (dst passed implicitly through g_xa below)
        extern __device__ char g_xa[];
        (void)0;
        // store
        // NOTE: tile index provided via rows pointer trick is not possible; see wrapper.
        // (actual store done in wrapper below)
        // -- replaced by wrapper; this function body is inlined there.
        (void)hv; (void)r; (void)Fl;
        break; // never used directly
    }
}
// actual A conversion (self-contained)
__device__ __forceinline__ void convert_a_tile256(const float* __restrict__ x,
                                                  int mt, int kc, const int* rows, int t) {
    char* dst = g_xa + ((size_t)(mt * NKC + kc)) * TILE_A;
#pragma unroll
    for (int i = 0; i < 16; i++) {
        int h = i * 256 + t;
        int r = h >> 5, Fl = h & 31;
        int grow = rows[r];
        uint2 hv = make_uint2(0u, 0u);
        if (grow >= 0) {
            float4 w = *(const float4*)(x + (size_t)grow * DIM + kc * BK + Fl * 4);
            __half2 h0 = __floats2half2_rn(w.x, w.y);
            __half2 h1 = __floats2half2_rn(w.z, w.w);
            hv.x = *(uint32_t*)&h0; hv.y = *(uint32_t*)&h1;
        }
        *(uint2*)(dst + ((Fl >> 4) << 14) + sw128((uint32_t)(r * 128 + (Fl & 15) * 8))) = hv;
    }
}

// ======================= K0: detect + reset =======================
__global__ void k0_reset_detect(const int* __restrict__ v32) {
    int i = blockIdx.x * 256 + threadIdx.x;          // 0..8191
    if ((i & 1) && v32[i] != 0) d_is64 = 0;
    for (int j = i; j < MAXTILES * 128; j += 8192) d_perm[j] = -1;
    if (i < MAXTILES * NKC) f_a[i] = 0;
    if (i < NEXP * NNT * NKC) f_b[i] = 0;
    if (i == 0) d_done = 0;
}

// ======================= K1: per-block hist + global scan =======================
__global__ void k1_hist_scan(const int* __restrict__ v32) {
    __shared__ int h[NEXP];
    const int t = threadIdx.x;
    const int b = blockIdx.x;
    if (t < NEXP) h[t] = 0;
    __syncthreads();
    int e = expert_of(v32, b * 256 + t);
    if (e >= 0 && e < NEXP) atomicAdd(&h[e], 1);
    __syncthreads();
    if (t < NEXP) d_bh[b][t] = h[t];
    __threadfence();
    if (t == 0) {
        int r = atomicAdd(&d_done, 1);
        if (r == NTB - 1) {
            int tot[NEXP];
            for (int ee = 0; ee < NEXP; ee++) {
                int s = 0;
                for (int bb = 0; bb < NTB; bb++) s += d_bh[bb][ee];
                tot[ee] = s;
            }
            int pacc = 0;
            d_poff[0] = 0;
            for (int ee = 0; ee < NEXP; ee++) {
                int base = pacc;
                pacc += ((tot[ee] + 127) / 128) * 128;
                d_poff[ee + 1] = pacc;
                int run = base;
                for (int bb = 0; bb < NTB; bb++) { d_boff[bb][ee] = run; run += d_bh[bb][ee]; }
            }
            d_done = 0;
            __threadfence();
        }
    }
}

// ======================= K2: deterministic scatter =======================
__global__ void k2_scatter(const int* __restrict__ v32) {
    __shared__ short se[256];
    const int t = threadIdx.x;
    const int tb = blockIdx.x;
    int e = expert_of(v32, tb * 256 + t);
    se[t] = (short)e;
    __syncthreads();
    int rank = 0;
    for (int j = 0; j < t; j++) rank += (se[j] == (short)e);
    if (e >= 0 && e < NEXP)
        d_perm[d_boff[tb][e] + rank] = tb * 256 + t;
}

// ======================= K3: self-converting grouped GEMM =======================
__device__ __forceinline__ void issue_stage(uint32_t A0, uint32_t mb, int chunk, int stage,
                                            int mt, int e, int nt) {
    uint32_t bar = mb + stage * 8;
    MBARRIER_EXPECT_TX(bar, (uint32_t)STAGE_SZ);
    const char* asrc = g_xa + ((size_t)(mt * NKC + chunk)) * TILE_A;
    const char* bsrc = g_wb + ((size_t)((e * NNT + nt) * NKC + chunk)) * TILE_B;
    uint32_t sb = A0 + stage * STAGE_SZ;
    bulk_g2s(sb, asrc, TILE_A, bar);
    bulk_g2s(sb + OFF_B, bsrc, TILE_B, bar);
}

__global__ void __launch_bounds__(GTHREADS, 1)
k_gemm(const float* __restrict__ x, const float* __restrict__ W,
       const float* __restrict__ bias, float* __restrict__ out)
{
    const int nt = blockIdx.x;
    const int mt = blockIdx.y;
    const int m0p = mt * BM;
    if (m0p >= d_poff[NEXP]) return;
    int e = 0;
#pragma unroll
    for (int i = 0; i < NEXP; i++) if (m0p >= d_poff[i + 1]) e = i + 1;
    const int n0 = nt * BN;

    extern __shared__ char smraw[];
    const uint32_t A0 = (smem_u32(smraw) + 1023u) & ~1023u;
    char* sbase = smraw + (A0 - smem_u32(smraw));
    const uint32_t mb = A0 + OFF_MB;
    int* rows = (int*)(sbase + OFF_ROWS);
    __shared__ int sclaim;

    const int tid = threadIdx.x;
    const int wid = tid >> 5;
    const int lane = tid & 31;
    const int warp_m = wid >> 2;     // 0..1 -> 64 m-rows
    const int warp_n = wid & 3;      // 0..3 -> 32 n-cols

    if (tid < BM) rows[tid] = d_perm[m0p + tid];
    if (tid == 0) {
        MBARRIER_INIT(mb, 1);
        MBARRIER_INIT(mb + 8, 1);
    }
    __syncthreads();

    // ---- ensure tile converted: CAS self-help, all 256 threads convert ----
    #define ENSURE_TILE(FPTR, CONVCALL) do {                                    \
        volatile int* _f = (FPTR);                                               \
        if (tid == 0) {                                                          \
            int _v = *_f;                                                        \
            if (_v == 2) sclaim = 0;                                             \
            else {                                                               \
                int _old = atomicCAS((int*)_f, 0, 1);                            \
                sclaim = (_old == 0) ? 1 : ((_old == 2) ? 0 : 2);                \
            }                                                                    \
        }                                                                        \
        __syncthreads();                                                         \
        int _cl = sclaim;                                                        \
        if (_cl == 1) {                                                          \
            CONVCALL;                                                            \
            __threadfence();                                                     \
            __syncthreads();                                                     \
            if (tid == 0) *_f = 2;                                               \
        } else if (_cl == 2) {                                                   \
            if (tid == 0) { while (*_f != 2) __nanosleep(32); }                  \
        }                                                                        \
        __syncthreads();                                                         \
    } while (0)

    #define ENSURE_CHUNK(KC) do {                                                \
        ENSURE_TILE(&f_b[(e * NNT + nt) * NKC + (KC)],                           \
                    convert_b_body(W, e, nt, (KC), tid));                        \
        ENSURE_TILE(&f_a[mt * NKC + (KC)],                                       \
                    convert_a_tile256(x, mt, (KC), rows, tid));                  \
    } while (0)

    ENSURE_CHUNK(0);
    if (tid == 0) {
        asm volatile("fence.proxy.async;" ::: "memory");
        issue_stage(A0, mb, 0, 0, mt, e, nt);
    }

    float acc[4][4][4];
#pragma unroll
    for (int i = 0; i < 4; i++)
#pragma unroll
        for (int j = 0; j < 4; j++)
#pragma unroll
            for (int q = 0; q < 4; q++) acc[i][j][q] = 0.0f;

    const int lrow = lane & 15;
    const int lc16 = (lane >> 4) << 4;
    uint32_t a0off[4];
#pragma unroll
    for (int i = 0; i < 4; i++)
        a0off[i] = sw128((uint32_t)((warp_m * 64 + i * 16 + lrow) * 128 + lc16));
    const int blk = lane >> 3;
    const int ng = blk & 1;
    const int base_k = (blk >> 1) * 8 + (lane & 7);
    uint32_t b0off[2];
#pragma unroll
    for (int g = 0; g < 2; g++) {
        int nn = (warp_n & 1) * 32 + g * 16 + ng * 8;
        b0off[g] = ((uint32_t)(warp_n >> 1) << 14)
                 + sw128((uint32_t)(base_k * 128 + nn * 2));
    }

    for (int c = 0; c < NKC; c++) {
        const int s = c & 1;
        if (c + 1 < NKC) {
            ENSURE_CHUNK(c + 1);
            if (tid == 0) {
                asm volatile("fence.proxy.async;" ::: "memory");
                issue_stage(A0, mb, c + 1, (c + 1) & 1, mt, e, nt);
            }
        }

        MBARRIER_WAIT_PARITY(mb + s * 8, (c >> 1) & 1);

        const uint32_t aA = A0 + s * STAGE_SZ;
        const uint32_t aB = aA + OFF_B;
#pragma unroll
        for (int ks = 0; ks < 8; ks++) {
            uint32_t bf[2][4];
            const uint32_t bofs = aB + ((uint32_t)ks << 11);
#pragma unroll
            for (int g = 0; g < 2; g++) ldsm_x4_t(bf[g], bofs + b0off[g]);
            const uint32_t asub = aA + ((uint32_t)(ks >> 2) << 14);
            const uint32_t akx = (uint32_t)((ks & 3) << 5);
#pragma unroll
            for (int i = 0; i < 4; i++) {
                uint32_t af[4];
                ldsm_x4(af, asub + (a0off[i] ^ akx));
#pragma unroll
                for (int j = 0; j < 4; j++)
                    mma16816(acc[i][j], af, bf[j >> 1][j & 1], bf[j >> 1][(j & 1) + 2]);
            }
        }
        __syncthreads();
    }

    // epilogue: add bias, scatter rows
    const float* be = bias + (size_t)e * DIM;
#pragma unroll
    for (int i = 0; i < 4; i++) {
#pragma unroll
        for (int half = 0; half < 2; half++) {
            int mloc = warp_m * 64 + i * 16 + (lane >> 2) + half * 8;
            int grow = rows[mloc];
            if (grow < 0) continue;
            float* orow = out + (size_t)grow * DIM;
#pragma unroll
            for (int j = 0; j < 4; j++) {
                int col = n0 + warp_n * 32 + j * 8 + (lane & 3) * 2;
                float2 bb = *(const float2*)(be + col);
                float2 o;
                o.x = acc[i][j][half * 2 + 0] + bb.x;
                o.y = acc[i][j][half * 2 + 1] + bb.y;
                *(float2*)(orow + col) = o;
            }
        }
    }
    #undef ENSURE_CHUNK
    #undef ENSURE_TILE
}

// ======================= host =======================
extern "C" void kernel_launch(void* const* d_in, const int* in_sizes, int n_in,
                              void* d_out, int out_size)
{
    const float* x = nullptr;
    const float* W = nullptr;
    const float* b = nullptr;
    const void* idx = nullptr;
    for (int i = 0; i < n_in; i++) {
        long long sz = in_sizes[i];
        if      (sz == (long long)B_TOK * DIM)      x = (const float*)d_in[i];
        else if (sz == (long long)NEXP * DIM * DIM) W = (const float*)d_in[i];
        else if (sz == (long long)NEXP * DIM)       b = (const float*)d_in[i];
        else if (sz == (long long)B_TOK)            idx = d_in[i];
    }
    float* out = (float*)d_out;
    const int* v32 = (const int*)idx;

    cudaFuncSetAttribute(k_gemm, cudaFuncAttributeMaxDynamicSharedMemorySize, SMEM_REQ);

    k0_reset_detect<<<32, 256>>>(v32);               // launch 1
    k1_hist_scan<<<NTB, 256>>>(v32);                 // launch 2
    k2_scatter<<<NTB, 256>>>(v32);                   // launch 3
    dim3 ggrid(NNT, MAXTILES);                       // (16, 72)
    k_gemm<<<ggrid, GTHREADS, SMEM_REQ>>>(x, W, b, out);   // launch 4 (ncu target)
}

// round 16
// speedup vs baseline: 2.5281x; 2.5281x over previous
#include <cuda_runtime.h>
#include <cuda_fp16.h>
#include <stdint.h>

#define B_TOK 8192
#define DIM   2048
#define NEXP  8

#define BM 128
#define BN 256
#define BK 128
#define NKC (DIM / BK)          // 16
#define NNT (DIM / BN)          // 8
#define MAXTILES 72
#define STAGES 2
#define GTHREADS 512            // 16 compute warps

#define TILE_A 32768            // 128m x 128k fp16, 2 k-subtiles of 16KB, SW128
#define TILE_B 65536            // 128k x 256n fp16, 4 n-subtiles of 16KB, SW128
#define STAGE_SZ (TILE_A + TILE_B)      // 98304
#define OFF_B TILE_A
#define OFF_MB (STAGES * STAGE_SZ)      // 196608
#define OFF_ROWS (OFF_MB + 64)
#define SMEM_REQ (OFF_ROWS + 512 + 1024)

#define NTB 32

// -------- device scratch --------
__device__ int d_bh[NTB][NEXP];
__device__ int d_boff[NTB][NEXP];
__device__ int d_poff[NEXP + 1];
__device__ int d_is64 = 1;           // monotone latch
__device__ int d_done = 0;
__device__ int d_perm[MAXTILES * 128];

__device__ __align__(128) char g_xa[(size_t)MAXTILES * NKC * TILE_A];
__device__ __align__(128) char g_wb[(size_t)NEXP * NNT * NKC * TILE_B];

// ======================= helpers =======================
__device__ __forceinline__ uint32_t smem_u32(const void* p) {
    uint32_t a;
    asm("{ .reg .u64 t; cvta.to.shared.u64 t, %1; cvt.u32.u64 %0, t; }" : "=r"(a) : "l"(p));
    return a;
}
__device__ __forceinline__ uint32_t sw128(uint32_t off) { return off ^ ((off >> 3) & 0x70); }

__device__ __forceinline__ void ldsm_x4(uint32_t* r, uint32_t addr) {
    asm volatile("ldmatrix.sync.aligned.m8n8.x4.shared.b16 {%0,%1,%2,%3}, [%4];"
                 : "=r"(r[0]), "=r"(r[1]), "=r"(r[2]), "=r"(r[3]) : "r"(addr));
}
__device__ __forceinline__ void ldsm_x4_t(uint32_t* r, uint32_t addr) {
    asm volatile("ldmatrix.sync.aligned.m8n8.x4.trans.shared.b16 {%0,%1,%2,%3}, [%4];"
                 : "=r"(r[0]), "=r"(r[1]), "=r"(r[2]), "=r"(r[3]) : "r"(addr));
}
__device__ __forceinline__ void mma16816(float* d, const uint32_t* a, uint32_t b0, uint32_t b1) {
    asm volatile(
        "mma.sync.aligned.m16n8k16.row.col.f32.f16.f16.f32 "
        "{%0,%1,%2,%3}, {%4,%5,%6,%7}, {%8,%9}, {%0,%1,%2,%3};"
        : "+f"(d[0]), "+f"(d[1]), "+f"(d[2]), "+f"(d[3])
        : "r"(a[0]), "r"(a[1]), "r"(a[2]), "r"(a[3]), "r"(b0), "r"(b1));
}
__device__ __forceinline__ void bulk_g2s(uint32_t dst, const void* src, uint32_t bytes, uint32_t mbar) {
    asm volatile(
        "{\n\t.reg .u64 g;\n\tcvta.to.global.u64 g, %1;\n\t"
        "cp.async.bulk.shared::cluster.global.mbarrier::complete_tx::bytes [%0], [g], %2, [%3];\n\t}"
        :: "r"(dst), "l"(src), "r"(bytes), "r"(mbar) : "memory");
}
#define MBARRIER_INIT(addr, cnt) \
    asm volatile("mbarrier.init.shared.b64 [%0], %1;" :: "r"((uint32_t)(addr)), "r"((uint32_t)(cnt)) : "memory")
#define MBARRIER_EXPECT_TX(addr, tx) \
    asm volatile("mbarrier.arrive.expect_tx.shared.b64 _, [%0], %1;" :: "r"((uint32_t)(addr)), "r"((uint32_t)(tx)) : "memory")
#define MBARRIER_WAIT_PARITY(addr, par) do { \
    uint32_t _m = (uint32_t)(addr); uint32_t _p = (uint32_t)(par); uint32_t _done; \
    asm volatile("{\n\t.reg .pred p;\n\t" \
        "mbarrier.try_wait.parity.acquire.cta.shared::cta.b64 p, [%1], %2;\n\t" \
        "selp.b32 %0, 1, 0, p;\n\t}" : "=r"(_done) : "r"(_m), "r"(_p) : "memory"); \
    if (!_done) { \
        asm volatile("{\n\t.reg .pred P1;\n\t" \
            "WL_%=:\n\tmbarrier.try_wait.parity.acquire.cta.shared::cta.b64 P1, [%0], %1, 0x989680;\n\t" \
            "@P1 bra.uni WD_%=;\n\tbra.uni WL_%=;\n\tWD_%=:\n\t}" \
            :: "r"(_m), "r"(_p) : "memory"); \
    } \
} while (0)

__device__ __forceinline__ int expert_of(const int* v, int i) { return d_is64 ? v[2 * i] : v[i]; }

// ======================= K1: convw (K-major, coalesced) + init + detect =======================
// B tile (e,nt,kc): [128k x 256n] fp16, 4 n-subtiles of (128k x 64n), SW128.
__global__ void k1_convw_init(const float* __restrict__ W, const int* __restrict__ v32) {
    const int bid = blockIdx.x + NNT * (blockIdx.y + NKC * blockIdx.z);  // 0..1023
    const int t = threadIdx.x;

    if (bid < 36) {
        int i = bid * 256 + t;
        if (i < MAXTILES * 128) d_perm[i] = -1;
        if (bid == 0 && t == 0) d_done = 0;
    }
    if (bid >= 64 && bid < 96) {
        int i = (bid - 64) * 256 + t;
        if ((i & 1) && v32[i] != 0) d_is64 = 0;
    }

    const int nt = blockIdx.x, kc = blockIdx.y, e = blockIdx.z;
    const float* Wb = W + ((size_t)e * DIM + kc * BK) * DIM + nt * BN;
    char* dst = g_wb + ((size_t)((e * NNT + nt) * NKC + kc)) * TILE_B;

#pragma unroll
    for (int i = 0; i < 16; i++) {
        int g = i * 256 + t;               // 0..4095 granules of 8 n (32B fp32)
        int k = g >> 5;                    // 0..127
        int c = g & 31;                    // n = c*8
        const float4* s4 = (const float4*)(Wb + (size_t)k * DIM + c * 8);
        float4 w0 = s4[0];
        float4 w1 = s4[1];
        __half2 h0 = __floats2half2_rn(w0.x, w0.y);
        __half2 h1 = __floats2half2_rn(w0.z, w0.w);
        __half2 h2 = __floats2half2_rn(w1.x, w1.y);
        __half2 h3 = __floats2half2_rn(w1.z, w1.w);
        uint4 val;
        val.x = *(uint32_t*)&h0; val.y = *(uint32_t*)&h1;
        val.z = *(uint32_t*)&h2; val.w = *(uint32_t*)&h3;
        *(uint4*)(dst + ((c >> 3) << 14) + sw128((uint32_t)(k * 128 + (c & 7) * 16))) = val;
    }
}

// ======================= K2: per-block hist + global scan =======================
__global__ void k2_hist_scan(const int* __restrict__ v32) {
    __shared__ int h[NEXP];
    const int t = threadIdx.x;
    const int b = blockIdx.x;
    if (t < NEXP) h[t] = 0;
    __syncthreads();
    int e = expert_of(v32, b * 256 + t);
    if (e >= 0 && e < NEXP) atomicAdd(&h[e], 1);
    __syncthreads();
    if (t < NEXP) d_bh[b][t] = h[t];
    __threadfence();
    if (t == 0) {
        int r = atomicAdd(&d_done, 1);
        if (r == NTB - 1) {
            int tot[NEXP];
            for (int ee = 0; ee < NEXP; ee++) {
                int s = 0;
                for (int bb = 0; bb < NTB; bb++) s += d_bh[bb][ee];
                tot[ee] = s;
            }
            int pacc = 0;
            d_poff[0] = 0;
            for (int ee = 0; ee < NEXP; ee++) {
                int base = pacc;
                pacc += ((tot[ee] + 127) / 128) * 128;
                d_poff[ee + 1] = pacc;
                int run = base;
                for (int bb = 0; bb < NTB; bb++) { d_boff[bb][ee] = run; run += d_bh[bb][ee]; }
            }
            d_done = 0;
            __threadfence();
        }
    }
}

// ======================= K3: deterministic scatter (perm only) =======================
__global__ void k3_scatter(const int* __restrict__ v32) {
    __shared__ short se[256];
    const int t = threadIdx.x;
    const int tb = blockIdx.x;
    int e = expert_of(v32, tb * 256 + t);
    se[t] = (short)e;
    __syncthreads();
    int rank = 0;
    for (int j = 0; j < t; j++) rank += (se[j] == (short)e);
    if (e >= 0 && e < NEXP)
        d_perm[d_boff[tb][e] + rank] = tb * 256 + t;
}

// ======================= K4: A conversion, one tile per CTA (wide grid) =======================
// A tile (mt,kc): [128m x 128k] fp16, 2 k-subtiles of (128m x 64k), SW128.
__global__ void k4_convx(const float* __restrict__ x) {
    const int mt = blockIdx.x, kc = blockIdx.y;
    if (mt * BM >= d_poff[NEXP]) return;
    __shared__ int rows[128];
    const int t = threadIdx.x;
    if (t < 128) rows[t] = d_perm[mt * 128 + t];
    __syncthreads();

    char* dst = g_xa + ((size_t)(mt * NKC + kc)) * TILE_A;
#pragma unroll
    for (int i = 0; i < 16; i++) {
        int h = i * 256 + t;                 // 0..4095 granules of 4 k (16B fp32)
        int r = h >> 5, Fl = h & 31;
        int grow = rows[r];
        uint2 hv = make_uint2(0u, 0u);
        if (grow >= 0) {
            float4 w = *(const float4*)(x + (size_t)grow * DIM + kc * BK + Fl * 4);
            __half2 h0 = __floats2half2_rn(w.x, w.y);
            __half2 h1 = __floats2half2_rn(w.z, w.w);
            hv.x = *(uint32_t*)&h0; hv.y = *(uint32_t*)&h1;
        }
        *(uint2*)(dst + ((Fl >> 4) << 14) + sw128((uint32_t)(r * 128 + (Fl & 15) * 8))) = hv;
    }
}

// ======================= K5: grouped GEMM (round-9 verbatim) =======================
__device__ __forceinline__ void issue_stage(uint32_t A0, uint32_t mb, int chunk, int stage,
                                            int mt, int e, int nt) {
    uint32_t bar = mb + stage * 8;
    MBARRIER_EXPECT_TX(bar, (uint32_t)STAGE_SZ);
    const char* asrc = g_xa + ((size_t)(mt * NKC + chunk)) * TILE_A;
    const char* bsrc = g_wb + ((size_t)((e * NNT + nt) * NKC + chunk)) * TILE_B;
    uint32_t sb = A0 + stage * STAGE_SZ;
    bulk_g2s(sb, asrc, TILE_A, bar);
    bulk_g2s(sb + OFF_B, bsrc, TILE_B, bar);
}

__global__ void __launch_bounds__(GTHREADS, 1)
k_gemm(const float* __restrict__ bias, float* __restrict__ out)
{
    const int m0p = blockIdx.y * BM;
    if (m0p >= d_poff[NEXP]) return;
    int e = 0;
#pragma unroll
    for (int i = 0; i < NEXP; i++) if (m0p >= d_poff[i + 1]) e = i + 1;

    const int mt = blockIdx.y;
    const int nt = blockIdx.x;
    const int n0 = nt * BN;

    extern __shared__ char smraw[];
    const uint32_t A0 = (smem_u32(smraw) + 1023u) & ~1023u;
    const uint32_t mb = A0 + OFF_MB;

    const int tid = threadIdx.x;
    const int wid = tid >> 5;
    const int lane = tid & 31;
    const int warp_m = wid >> 3;     // 0..1 -> 64 m-rows
    const int warp_n = wid & 7;      // 0..7 -> 32 n-cols

    int* rows = (int*)(smraw + ((A0 + OFF_ROWS) - smem_u32(smraw)));
    if (tid < BM) rows[tid] = d_perm[m0p + tid];
    if (tid == 0) {
        MBARRIER_INIT(mb, 1);
        MBARRIER_INIT(mb + 8, 1);
    }
    __syncthreads();

    if (tid == 0) issue_stage(A0, mb, 0, 0, mt, e, nt);

    float acc[4][4][4];
#pragma unroll
    for (int i = 0; i < 4; i++)
#pragma unroll
        for (int j = 0; j < 4; j++)
#pragma unroll
            for (int q = 0; q < 4; q++) acc[i][j][q] = 0.0f;

    const int lrow = lane & 15;
    const int lc16 = (lane >> 4) << 4;
    uint32_t a0off[4];
#pragma unroll
    for (int i = 0; i < 4; i++)
        a0off[i] = sw128((uint32_t)((warp_m * 64 + i * 16 + lrow) * 128 + lc16));

    const int blk = lane >> 3;
    const int ng = blk & 1;
    const int base_k = (blk >> 1) * 8 + (lane & 7);
    uint32_t b0off[2];
#pragma unroll
    for (int g = 0; g < 2; g++) {
        int nn = (warp_n & 1) * 32 + g * 16 + ng * 8;    // n within 64-subtile
        b0off[g] = ((uint32_t)(warp_n >> 1) << 14)
                 + sw128((uint32_t)(base_k * 128 + nn * 2));
    }

    for (int c = 0; c < NKC; c++) {
        const int s = c & 1;
        if (tid == 0 && c + 1 < NKC) issue_stage(A0, mb, c + 1, (c + 1) & 1, mt, e, nt);

        MBARRIER_WAIT_PARITY(mb + s * 8, (c >> 1) & 1);

        const uint32_t aA = A0 + s * STAGE_SZ;
        const uint32_t aB = aA + OFF_B;
#pragma unroll
        for (int ks = 0; ks < 8; ks++) {
            uint32_t af[4][4];
            const uint32_t asub = aA + ((uint32_t)(ks >> 2) << 14);
            const uint32_t akx = (uint32_t)((ks & 3) << 5);
#pragma unroll
            for (int i = 0; i < 4; i++) ldsm_x4(af[i], asub + (a0off[i] ^ akx));
            uint32_t bf[2][4];
            const uint32_t bofs = aB + ((uint32_t)ks << 11);
#pragma unroll
            for (int g = 0; g < 2; g++) ldsm_x4_t(bf[g], bofs + b0off[g]);
#pragma unroll
            for (int i = 0; i < 4; i++)
#pragma unroll
                for (int j = 0; j < 4; j++)
                    mma16816(acc[i][j], af[i], bf[j >> 1][j & 1], bf[j >> 1][(j & 1) + 2]);
        }
        __syncthreads();
    }

    // epilogue: add bias, scatter rows
    const float* be = bias + (size_t)e * DIM;
#pragma unroll
    for (int i = 0; i < 4; i++) {
#pragma unroll
        for (int half = 0; half < 2; half++) {
            int mloc = warp_m * 64 + i * 16 + (lane >> 2) + half * 8;
            int grow = rows[mloc];
            if (grow < 0) continue;
            float* orow = out + (size_t)grow * DIM;
#pragma unroll
            for (int j = 0; j < 4; j++) {
                int col = n0 + warp_n * 32 + j * 8 + (lane & 3) * 2;
                float2 bb = *(const float2*)(be + col);
                float2 o;
                o.x = acc[i][j][half * 2 + 0] + bb.x;
                o.y = acc[i][j][half * 2 + 1] + bb.y;
                *(float2*)(orow + col) = o;
            }
        }
    }
}

// ======================= host =======================
extern "C" void kernel_launch(void* const* d_in, const int* in_sizes, int n_in,
                              void* d_out, int out_size)
{
    const float* x = nullptr;
    const float* W = nullptr;
    const float* b = nullptr;
    const void* idx = nullptr;
    for (int i = 0; i < n_in; i++) {
        long long sz = in_sizes[i];
        if      (sz == (long long)B_TOK * DIM)      x = (const float*)d_in[i];
        else if (sz == (long long)NEXP * DIM * DIM) W = (const float*)d_in[i];
        else if (sz == (long long)NEXP * DIM)       b = (const float*)d_in[i];
        else if (sz == (long long)B_TOK)            idx = d_in[i];
    }
    float* out = (float*)d_out;
    const int* v32 = (const int*)idx;

    cudaFuncSetAttribute(k_gemm, cudaFuncAttributeMaxDynamicSharedMemorySize, SMEM_REQ);

    dim3 wgrid(NNT, NKC, NEXP);                      // 1024 CTAs
    k1_convw_init<<<wgrid, 256>>>(W, v32);           // launch 1
    k2_hist_scan<<<NTB, 256>>>(v32);                 // launch 2
    k3_scatter<<<NTB, 256>>>(v32);                   // launch 3
    dim3 agrid(MAXTILES, NKC);                       // (72, 16) = 1152 CTAs
    k4_convx<<<agrid, 256>>>(x);                     // launch 4
    dim3 ggrid(NNT, MAXTILES);                       // (8, 72)
    k_gemm<<<ggrid, GTHREADS, SMEM_REQ>>>(b, out);   // launch 5
}